// round 6
// baseline (speedup 1.0000x reference)
#include <cuda_runtime.h>
#include <cuda_bf16.h>

#define LL   512
#define BSZ  32
#define LP1  513
#define ROWF 1539
#define RCA  3.8f

// Scratch: Fa (12 floats, 3x4 row-major) + Fb (12 floats) per (b, l)
__device__ float g_F[BSZ * LL * 24];
__device__ int   g_ready[BSZ];   // zero-init; restored to 0 at end of kernel
__device__ int   g_done[BSZ];    // zero-init; restored to 0 at end of kernel

// Affine 3x4 stored as r[0..8] row-major + t[9..11]. C = A @ B.
__device__ __forceinline__ void compose(const float* __restrict__ A,
                                        const float* __restrict__ B,
                                        float* __restrict__ C) {
#pragma unroll
    for (int i = 0; i < 3; i++) {
        const float a0 = A[i * 3 + 0], a1 = A[i * 3 + 1], a2 = A[i * 3 + 2];
        C[i * 3 + 0] = a0 * B[0] + a1 * B[3] + a2 * B[6];
        C[i * 3 + 1] = a0 * B[1] + a1 * B[4] + a2 * B[7];
        C[i * 3 + 2] = a0 * B[2] + a1 * B[5] + a2 * B[8];
        C[9 + i]     = a0 * B[9] + a1 * B[10] + a2 * B[11] + A[9 + i];
    }
}

union SmemU {
    float wTot[16][13];                         // scan path
    struct {                                    // emit path
        float4 sC[LP1];
        float  sV[2][1544];
        float  sFs[24];
    } e;
};

__device__ void scan_path(const float* __restrict__ angles, int b, SmemU* sm) {
    const int l    = threadIdx.x;
    const int w    = l >> 5;
    const int lane = l & 31;

    const float alpha = angles[(b * 2 + 0) * LL + l];
    const float beta  = angles[(b * 2 + 1) * LL + l];
    float sa, ca, sb, cb;
    sincosf(alpha, &sa, &ca);
    sincosf(beta,  &sb, &cb);

    float M[12];
    M[0] = ca;  M[1] = -sa * cb; M[2] = sa * sb;
    M[3] = sa;  M[4] = ca * cb;  M[5] = -ca * sb;
    M[6] = 0.f; M[7] = sb;       M[8] = cb;
    M[9] = RCA * ca; M[10] = RCA * sa; M[11] = 0.f;

#pragma unroll
    for (int off = 1; off < 32; off <<= 1) {
        float Lf[12];
#pragma unroll
        for (int k = 0; k < 12; k++) Lf[k] = __shfl_up_sync(0xffffffffu, M[k], off);
        if (lane >= off) {
            float T[12];
            compose(Lf, M, T);
#pragma unroll
            for (int k = 0; k < 12; k++) M[k] = T[k];
        }
    }
    if (lane == 31) {
#pragma unroll
        for (int k = 0; k < 12; k++) sm->wTot[w][k] = M[k];
    }
    __syncthreads();

    if (w == 0) {
        float S[12];
        if (lane < 16) {
#pragma unroll
            for (int k = 0; k < 12; k++) S[k] = sm->wTot[lane][k];
        } else {
            S[0] = 1.f; S[1] = 0.f; S[2] = 0.f;
            S[3] = 0.f; S[4] = 1.f; S[5] = 0.f;
            S[6] = 0.f; S[7] = 0.f; S[8] = 1.f;
            S[9] = 0.f; S[10] = 0.f; S[11] = 0.f;
        }
#pragma unroll
        for (int off = 1; off < 16; off <<= 1) {
            float Lf[12];
#pragma unroll
            for (int k = 0; k < 12; k++) Lf[k] = __shfl_up_sync(0xffffffffu, S[k], off);
            if (lane >= off && lane < 16) {
                float T[12];
                compose(Lf, S, T);
#pragma unroll
                for (int k = 0; k < 12; k++) S[k] = T[k];
            }
        }
        if (lane < 16) {
#pragma unroll
            for (int k = 0; k < 12; k++) sm->wTot[lane][k] = S[k];
        }
    }
    __syncthreads();

    float Fin[12];
    if (w > 0) {
        float P[12];
#pragma unroll
        for (int k = 0; k < 12; k++) P[k] = sm->wTot[w - 1][k];
        compose(P, M, Fin);
    } else {
#pragma unroll
        for (int k = 0; k < 12; k++) Fin[k] = M[k];
    }

    float Mp[12];
#pragma unroll
    for (int k = 0; k < 9; k++) Mp[k] = __shfl_up_sync(0xffffffffu, Fin[k], 1);
    if (lane == 0) {
        if (w == 0) {
            Mp[0] = 1.f; Mp[1] = 0.f; Mp[2] = 0.f;
            Mp[3] = 0.f; Mp[4] = 1.f; Mp[5] = 0.f;
            Mp[6] = 0.f; Mp[7] = 0.f; Mp[8] = 1.f;
        } else {
#pragma unroll
            for (int k = 0; k < 9; k++) Mp[k] = sm->wTot[w - 1][k];
        }
    }
    Mp[9] = 0.f; Mp[10] = 0.f; Mp[11] = 0.f;

    float Mi[12];
    Mi[0] = Fin[0]; Mi[1] = Fin[3]; Mi[2] = Fin[6];
    Mi[3] = Fin[1]; Mi[4] = Fin[4]; Mi[5] = Fin[7];
    Mi[6] = Fin[2]; Mi[7] = Fin[5]; Mi[8] = Fin[8];
    Mi[9]  = -(Mi[0] * Fin[9] + Mi[1] * Fin[10] + Mi[2] * Fin[11]);
    Mi[10] = -(Mi[3] * Fin[9] + Mi[4] * Fin[10] + Mi[5] * Fin[11]);
    Mi[11] = -(Mi[6] * Fin[9] + Mi[7] * Fin[10] + Mi[8] * Fin[11]);

    float Da[12];
    Da[0] = -sa; Da[1] = -ca * cb; Da[2] = ca * sb;
    Da[3] = ca;  Da[4] = -sa * cb; Da[5] = sa * sb;
    Da[6] = 0.f; Da[7] = 0.f;      Da[8] = 0.f;
    Da[9] = -RCA * sa; Da[10] = RCA * ca; Da[11] = 0.f;

    float Db[12];
    Db[0] = 0.f; Db[1] = sa * sb;  Db[2] = sa * cb;
    Db[3] = 0.f; Db[4] = -ca * sb; Db[5] = -ca * cb;
    Db[6] = 0.f; Db[7] = cb;       Db[8] = -sb;
    Db[9] = 0.f; Db[10] = 0.f;     Db[11] = 0.f;

    float G[12], Fa[12], Fb[12];
    compose(Da, Mi, G);
    compose(Mp, G, Fa);
    compose(Db, Mi, G);
    compose(Mp, G, Fb);

    float* o = &g_F[(b * LL + l) * 24];
#pragma unroll
    for (int i = 0; i < 3; i++) {
        o[i * 4 + 0] = Fa[i * 3 + 0];
        o[i * 4 + 1] = Fa[i * 3 + 1];
        o[i * 4 + 2] = Fa[i * 3 + 2];
        o[i * 4 + 3] = Fa[9 + i];
        o[12 + i * 4 + 0] = Fb[i * 3 + 0];
        o[12 + i * 4 + 1] = Fb[i * 3 + 1];
        o[12 + i * 4 + 2] = Fb[i * 3 + 2];
        o[12 + i * 4 + 3] = Fb[9 + i];
    }

    __threadfence();
    __syncthreads();
    if (threadIdx.x == 0) atomicExch(&g_ready[b], 1);
}

__device__ void emit_path(const float* __restrict__ coords,
                          const int* __restrict__ lens,
                          float* __restrict__ out,
                          int eid, SmemU* sm) {
    const int b   = eid >> 7;          // 128 emit blocks per batch
    const int l0  = (eid & 127) << 2;  // 4 l-values per block
    const int tid = threadIdx.x;

    // Overlap coord tile load with waiting for the scan flag.
    for (int m = tid; m < LP1; m += 512) {
        const float* c = coords + (size_t)b * ROWF + m * 3;
        sm->e.sC[m] = make_float4(c[0], c[1], c[2], 1.f);
    }
    const int len = lens[b];

    if (tid == 0) {
        while (atomicAdd(&g_ready[b], 0) == 0) __nanosleep(64);
    }
    __syncthreads();
    __threadfence();   // order g_F reads after observed flag

#pragma unroll 1
    for (int dl = 0; dl < 4; dl++) {
        const int l = l0 + dl;
        if (tid < 24) sm->e.sFs[tid] = g_F[(b * LL + l) * 24 + tid];
        __syncthreads();   // sFs ready; previous phase-2 done with sV

        float Fr[24];
#pragma unroll
        for (int k = 0; k < 24; k++) Fr[k] = sm->e.sFs[k];

        const int  ao    = (3 * l) & 3;
        const int  head  = (4 - ao) & 3;
        const bool alive = (l < len);

        // Phase 1: per-m compute, staged into smem at shift ao
        for (int m = tid; m < LP1; m += 512) {
            const float4 p = sm->e.sC[m];
            const bool on = alive && (m > l) && (m <= len);
            float a0 = 0.f, a1 = 0.f, a2 = 0.f, b0 = 0.f, b1 = 0.f, b2 = 0.f;
            if (on) {
                a0 = Fr[0]  * p.x + Fr[1]  * p.y + Fr[2]  * p.z + Fr[3];
                a1 = Fr[4]  * p.x + Fr[5]  * p.y + Fr[6]  * p.z + Fr[7];
                a2 = Fr[8]  * p.x + Fr[9]  * p.y + Fr[10] * p.z + Fr[11];
                b0 = Fr[12] * p.x + Fr[13] * p.y + Fr[14] * p.z + Fr[15];
                b1 = Fr[16] * p.x + Fr[17] * p.y + Fr[18] * p.z + Fr[19];
                b2 = Fr[20] * p.x + Fr[21] * p.y + Fr[22] * p.z + Fr[23];
            }
            const int s = ao + 3 * m;
            sm->e.sV[0][s]     = a0; sm->e.sV[0][s + 1] = a1; sm->e.sV[0][s + 2] = a2;
            sm->e.sV[1][s]     = b0; sm->e.sV[1][s + 1] = b1; sm->e.sV[1][s + 2] = b2;
        }
        __syncthreads();

        // Phase 2: aligned float4 copy (384 vec4 per row) + boundary scalars
        const size_t base0 = ((size_t)(b * 2 + 0) * LL + l) * ROWF;
        const size_t base1 = base0 + (size_t)LL * ROWF;
        const int s0 = ao + head;   // 0 or 4

        for (int t = tid; t < 768; t += 512) {
            const int row = (t >= 384);
            const int v   = t - (row << 8) - (row << 7);  // t - row*384
            const float4 val = *(const float4*)&sm->e.sV[row][s0 + 4 * v];
            float* gp = out + (row ? base1 : base0) + head + 4 * v;
            *(float4*)gp = val;
        }
        if (tid < 6) {
            const int row = tid / 3;
            const int j   = tid - row * 3;
            const int e   = (j < head) ? j : (1536 + j);
            out[(row ? base1 : base0) + e] = sm->e.sV[row][ao + e];
        }
    }

    // Reset handshake state for the next graph replay.
    __syncthreads();
    if (tid == 0) {
        const int d = atomicAdd(&g_done[b], 1);
        if (d == 127) {
            g_done[b]  = 0;
            g_ready[b] = 0;
        }
    }
}

__global__ __launch_bounds__(512) void fused_kernel(const float* __restrict__ angles,
                                                    const float* __restrict__ coords,
                                                    const int* __restrict__ lens,
                                                    float* __restrict__ out) {
    __shared__ SmemU sm;
    const int bid = blockIdx.x;
    if (bid < BSZ) {
        scan_path(angles, bid, &sm);
    } else {
        emit_path(coords, lens, out, bid - BSZ, &sm);
    }
}

extern "C" void kernel_launch(void* const* d_in, const int* in_sizes, int n_in,
                              void* d_out, int out_size) {
    const float* angles = (const float*)d_in[0];   // (32, 2, 512)
    const float* coords = (const float*)d_in[1];   // (32, 1539)
    const int*   lens   = (const int*)d_in[2];     // (32,)
    float* out = (float*)d_out;

    fused_kernel<<<BSZ + BSZ * (LL / 4), 512>>>(angles, coords, lens, out);
}

// round 9
// speedup vs baseline: 2.0115x; 2.0115x over previous
#include <cuda_runtime.h>
#include <cuda_bf16.h>

#define LL   512
#define BSZ  32
#define LP1  513
#define ROWF 1539
#define RCA  3.8f

// Scratch: Fa (12 floats, 3x4 row-major) + Fb (12 floats) per (b, l)
__device__ float g_F[BSZ * LL * 24];
// Homogeneous coords table: g_C4[b*513 + m] = (x, y, z, 1)
__device__ __align__(16) float4 g_C4[BSZ * LP1];

// Affine 3x4 stored as r[0..8] row-major + t[9..11]. C = A @ B.
__device__ __forceinline__ void compose(const float* __restrict__ A,
                                        const float* __restrict__ B,
                                        float* __restrict__ C) {
#pragma unroll
    for (int i = 0; i < 3; i++) {
        const float a0 = A[i * 3 + 0], a1 = A[i * 3 + 1], a2 = A[i * 3 + 2];
        C[i * 3 + 0] = a0 * B[0] + a1 * B[3] + a2 * B[6];
        C[i * 3 + 1] = a0 * B[1] + a1 * B[4] + a2 * B[7];
        C[i * 3 + 2] = a0 * B[2] + a1 * B[5] + a2 * B[8];
        C[9 + i]     = a0 * B[9] + a1 * B[10] + a2 * B[11] + A[9 + i];
    }
}

// One block per batch: builds coord table + warp-shuffle prefix product,
// then Fa/Fb = Rprev @ (dB @ Minv) per l.
__global__ __launch_bounds__(LL) void scan_kernel(const float* __restrict__ angles,
                                                  const float* __restrict__ coords) {
    __shared__ float wTot[16][13];
    const int b    = blockIdx.x;
    const int l    = threadIdx.x;
    const int w    = l >> 5;
    const int lane = l & 31;

    // Build homogeneous coord table (m = l and m = l + 512 for l == 0)
    {
        const float* c = coords + (size_t)b * ROWF + 3 * l;
        g_C4[b * LP1 + l] = make_float4(c[0], c[1], c[2], 1.f);
        if (l == 0) {
            const float* c2 = coords + (size_t)b * ROWF + 3 * 512;
            g_C4[b * LP1 + 512] = make_float4(c2[0], c2[1], c2[2], 1.f);
        }
    }

    const float alpha = angles[(b * 2 + 0) * LL + l];
    const float beta  = angles[(b * 2 + 1) * LL + l];
    float sa, ca, sb, cb;
    sincosf(alpha, &sa, &ca);
    sincosf(beta,  &sb, &cb);

    float M[12];
    M[0] = ca;  M[1] = -sa * cb; M[2] = sa * sb;
    M[3] = sa;  M[4] = ca * cb;  M[5] = -ca * sb;
    M[6] = 0.f; M[7] = sb;       M[8] = cb;
    M[9] = RCA * ca; M[10] = RCA * sa; M[11] = 0.f;

#pragma unroll
    for (int off = 1; off < 32; off <<= 1) {
        float Lf[12];
#pragma unroll
        for (int k = 0; k < 12; k++) Lf[k] = __shfl_up_sync(0xffffffffu, M[k], off);
        if (lane >= off) {
            float T[12];
            compose(Lf, M, T);
#pragma unroll
            for (int k = 0; k < 12; k++) M[k] = T[k];
        }
    }
    if (lane == 31) {
#pragma unroll
        for (int k = 0; k < 12; k++) wTot[w][k] = M[k];
    }
    __syncthreads();

    if (w == 0) {
        float S[12];
        if (lane < 16) {
#pragma unroll
            for (int k = 0; k < 12; k++) S[k] = wTot[lane][k];
        } else {
            S[0] = 1.f; S[1] = 0.f; S[2] = 0.f;
            S[3] = 0.f; S[4] = 1.f; S[5] = 0.f;
            S[6] = 0.f; S[7] = 0.f; S[8] = 1.f;
            S[9] = 0.f; S[10] = 0.f; S[11] = 0.f;
        }
#pragma unroll
        for (int off = 1; off < 16; off <<= 1) {
            float Lf[12];
#pragma unroll
            for (int k = 0; k < 12; k++) Lf[k] = __shfl_up_sync(0xffffffffu, S[k], off);
            if (lane >= off && lane < 16) {
                float T[12];
                compose(Lf, S, T);
#pragma unroll
                for (int k = 0; k < 12; k++) S[k] = T[k];
            }
        }
        if (lane < 16) {
#pragma unroll
            for (int k = 0; k < 12; k++) wTot[lane][k] = S[k];
        }
    }
    __syncthreads();

    float Fin[12];
    if (w > 0) {
        float P[12];
#pragma unroll
        for (int k = 0; k < 12; k++) P[k] = wTot[w - 1][k];
        compose(P, M, Fin);
    } else {
#pragma unroll
        for (int k = 0; k < 12; k++) Fin[k] = M[k];
    }

    float Mp[12];
#pragma unroll
    for (int k = 0; k < 9; k++) Mp[k] = __shfl_up_sync(0xffffffffu, Fin[k], 1);
    if (lane == 0) {
        if (w == 0) {
            Mp[0] = 1.f; Mp[1] = 0.f; Mp[2] = 0.f;
            Mp[3] = 0.f; Mp[4] = 1.f; Mp[5] = 0.f;
            Mp[6] = 0.f; Mp[7] = 0.f; Mp[8] = 1.f;
        } else {
#pragma unroll
            for (int k = 0; k < 9; k++) Mp[k] = wTot[w - 1][k];
        }
    }
    Mp[9] = 0.f; Mp[10] = 0.f; Mp[11] = 0.f;

    float Mi[12];
    Mi[0] = Fin[0]; Mi[1] = Fin[3]; Mi[2] = Fin[6];
    Mi[3] = Fin[1]; Mi[4] = Fin[4]; Mi[5] = Fin[7];
    Mi[6] = Fin[2]; Mi[7] = Fin[5]; Mi[8] = Fin[8];
    Mi[9]  = -(Mi[0] * Fin[9] + Mi[1] * Fin[10] + Mi[2] * Fin[11]);
    Mi[10] = -(Mi[3] * Fin[9] + Mi[4] * Fin[10] + Mi[5] * Fin[11]);
    Mi[11] = -(Mi[6] * Fin[9] + Mi[7] * Fin[10] + Mi[8] * Fin[11]);

    float Da[12];
    Da[0] = -sa; Da[1] = -ca * cb; Da[2] = ca * sb;
    Da[3] = ca;  Da[4] = -sa * cb; Da[5] = sa * sb;
    Da[6] = 0.f; Da[7] = 0.f;      Da[8] = 0.f;
    Da[9] = -RCA * sa; Da[10] = RCA * ca; Da[11] = 0.f;

    float Db[12];
    Db[0] = 0.f; Db[1] = sa * sb;  Db[2] = sa * cb;
    Db[3] = 0.f; Db[4] = -ca * sb; Db[5] = -ca * cb;
    Db[6] = 0.f; Db[7] = cb;       Db[8] = -sb;
    Db[9] = 0.f; Db[10] = 0.f;     Db[11] = 0.f;

    float G[12], Fa[12], Fb[12];
    compose(Da, Mi, G);
    compose(Mp, G, Fa);
    compose(Db, Mi, G);
    compose(Mp, G, Fb);

    float* o = &g_F[(b * LL + l) * 24];
#pragma unroll
    for (int i = 0; i < 3; i++) {
        o[i * 4 + 0] = Fa[i * 3 + 0];
        o[i * 4 + 1] = Fa[i * 3 + 1];
        o[i * 4 + 2] = Fa[i * 3 + 2];
        o[i * 4 + 3] = Fa[9 + i];
        o[12 + i * 4 + 0] = Fb[i * 3 + 0];
        o[12 + i * 4 + 1] = Fb[i * 3 + 1];
        o[12 + i * 4 + 2] = Fb[i * 3 + 2];
        o[12 + i * 4 + 3] = Fb[9 + i];
    }
}

// Barrier-free, smem-free emit. Thread = one aligned float4 output group
// (spans exactly 2 coord points). 4 l-values per block; dead rows stream zeros.
__global__ __launch_bounds__(256) void emit_kernel(const int* __restrict__ lens,
                                                   float* __restrict__ out) {
    const int b   = blockIdx.y;
    const int l0  = blockIdx.x << 2;
    const int tid = threadIdx.x;
    const int len = __ldg(&lens[b]);
    const float4* C4 = g_C4 + b * LP1;

#pragma unroll 1
    for (int dl = 0; dl < 4; dl++) {
        const int l = l0 + dl;
        const size_t base0 = ((size_t)(b * 2 + 0) * LL + l) * ROWF;
        const size_t base1 = base0 + (size_t)LL * ROWF;
        const int head = (4 - ((3 * l) & 3)) & 3;   // 0..3
        const int NG   = (ROWF - head) >> 2;        // aligned groups per row

        if (l >= len) {
            // Dead row: pure zero streaming (warp-uniform branch).
            const float4 z = make_float4(0.f, 0.f, 0.f, 0.f);
            for (int t = tid; t < 2 * NG; t += 256) {
                const int s = (t >= NG);
                const int g = t - (s ? NG : 0);
                *(float4*)(out + (s ? base1 : base0) + head + 4 * g) = z;
            }
            if (tid < 6) {
                const int s  = tid >= 3;
                const int jj = tid - (s ? 3 : 0);
                const int e  = (jj < head) ? jj : (head + 4 * NG + (jj - head));
                out[(s ? base1 : base0) + e] = 0.f;
            }
            continue;
        }

        const float4* Fp = (const float4*)&g_F[(b * LL + l) * 24];

        for (int t = tid; t < 2 * NG; t += 256) {
            const int s = (t >= NG);
            const int g = t - (s ? NG : 0);
            const int e0 = head + 4 * g;
            const int m0 = e0 / 3;
            const int c0 = e0 - 3 * m0;

            const float4 F0 = __ldg(&Fp[s * 3 + 0]);
            const float4 F1 = __ldg(&Fp[s * 3 + 1]);
            const float4 F2 = __ldg(&Fp[s * 3 + 2]);
            const float4 q0 = __ldg(&C4[m0]);
            const float4 q1 = __ldg(&C4[m0 + 1]);

            const bool on0 = (m0 > l) && (m0 <= len);
            const bool on1 = (m0 + 1 > l) && (m0 + 1 <= len);

            const float d00 = on0 ? (F0.x * q0.x + F0.y * q0.y + F0.z * q0.z + F0.w) : 0.f;
            const float d01 = on0 ? (F1.x * q0.x + F1.y * q0.y + F1.z * q0.z + F1.w) : 0.f;
            const float d02 = on0 ? (F2.x * q0.x + F2.y * q0.y + F2.z * q0.z + F2.w) : 0.f;
            const float d10 = on1 ? (F0.x * q1.x + F0.y * q1.y + F0.z * q1.z + F0.w) : 0.f;
            const float d11 = on1 ? (F1.x * q1.x + F1.y * q1.y + F1.z * q1.z + F1.w) : 0.f;
            const float d12 = on1 ? (F2.x * q1.x + F2.y * q1.y + F2.z * q1.z + F2.w) : 0.f;

            float4 o4;
            o4.x = (c0 == 0) ? d00 : (c0 == 1) ? d01 : d02;
            o4.y = (c0 == 0) ? d01 : (c0 == 1) ? d02 : d10;
            o4.z = (c0 == 0) ? d02 : (c0 == 1) ? d10 : d11;
            o4.w = (c0 == 0) ? d10 : (c0 == 1) ? d11 : d12;

            *(float4*)(out + (s ? base1 : base0) + e0) = o4;
        }

        // 3 boundary scalars per row (head + tail = 3).
        if (tid < 6) {
            const int s  = tid >= 3;
            const int jj = tid - (s ? 3 : 0);
            const int e  = (jj < head) ? jj : (head + 4 * NG + (jj - head));
            const int m  = e / 3;
            const int c  = e - 3 * m;
            const bool on = (m > l) && (m <= len);
            float val = 0.f;
            if (on) {
                const float4 Fc = __ldg(&Fp[s * 3 + c]);
                const float4 q  = __ldg(&C4[m]);
                val = Fc.x * q.x + Fc.y * q.y + Fc.z * q.z + Fc.w;
            }
            out[(s ? base1 : base0) + e] = val;
        }
    }
}

extern "C" void kernel_launch(void* const* d_in, const int* in_sizes, int n_in,
                              void* d_out, int out_size) {
    const float* angles = (const float*)d_in[0];   // (32, 2, 512)
    const float* coords = (const float*)d_in[1];   // (32, 1539)
    const int*   lens   = (const int*)d_in[2];     // (32,)
    float* out = (float*)d_out;

    scan_kernel<<<BSZ, LL>>>(angles, coords);
    emit_kernel<<<dim3(LL / 4, BSZ), 256>>>(lens, out);
}

// round 10
// speedup vs baseline: 2.1434x; 1.0656x over previous
#include <cuda_runtime.h>
#include <cuda_bf16.h>

#define LL   512
#define BSZ  32
#define LP1  513
#define ROWF 1539
#define NG   384          // aligned float4 groups per row (same for all shifts)
#define RCA  3.8f

// Scratch: Fa (12 floats, 3x4 row-major) + Fb (12 floats) per (b, l)
__device__ float g_F[BSZ * LL * 24];
// Homogeneous coords table: g_C4[b*513 + m] = (x, y, z, 1)
__device__ __align__(16) float4 g_C4[BSZ * LP1];

// Affine 3x4 stored as r[0..8] row-major + t[9..11]. C = A @ B.
__device__ __forceinline__ void compose(const float* __restrict__ A,
                                        const float* __restrict__ B,
                                        float* __restrict__ C) {
#pragma unroll
    for (int i = 0; i < 3; i++) {
        const float a0 = A[i * 3 + 0], a1 = A[i * 3 + 1], a2 = A[i * 3 + 2];
        C[i * 3 + 0] = a0 * B[0] + a1 * B[3] + a2 * B[6];
        C[i * 3 + 1] = a0 * B[1] + a1 * B[4] + a2 * B[7];
        C[i * 3 + 2] = a0 * B[2] + a1 * B[5] + a2 * B[8];
        C[9 + i]     = a0 * B[9] + a1 * B[10] + a2 * B[11] + A[9 + i];
    }
}

// One block per batch: builds coord table + warp-shuffle prefix product,
// then Fa/Fb = Rprev @ (dB @ Minv) per l.
__global__ __launch_bounds__(LL) void scan_kernel(const float* __restrict__ angles,
                                                  const float* __restrict__ coords) {
    __shared__ float wTot[16][13];
    const int b    = blockIdx.x;
    const int l    = threadIdx.x;
    const int w    = l >> 5;
    const int lane = l & 31;

    {
        const float* c = coords + (size_t)b * ROWF + 3 * l;
        g_C4[b * LP1 + l] = make_float4(c[0], c[1], c[2], 1.f);
        if (l == 0) {
            const float* c2 = coords + (size_t)b * ROWF + 3 * 512;
            g_C4[b * LP1 + 512] = make_float4(c2[0], c2[1], c2[2], 1.f);
        }
    }

    const float alpha = angles[(b * 2 + 0) * LL + l];
    const float beta  = angles[(b * 2 + 1) * LL + l];
    float sa, ca, sb, cb;
    sincosf(alpha, &sa, &ca);
    sincosf(beta,  &sb, &cb);

    float M[12];
    M[0] = ca;  M[1] = -sa * cb; M[2] = sa * sb;
    M[3] = sa;  M[4] = ca * cb;  M[5] = -ca * sb;
    M[6] = 0.f; M[7] = sb;       M[8] = cb;
    M[9] = RCA * ca; M[10] = RCA * sa; M[11] = 0.f;

#pragma unroll
    for (int off = 1; off < 32; off <<= 1) {
        float Lf[12];
#pragma unroll
        for (int k = 0; k < 12; k++) Lf[k] = __shfl_up_sync(0xffffffffu, M[k], off);
        if (lane >= off) {
            float T[12];
            compose(Lf, M, T);
#pragma unroll
            for (int k = 0; k < 12; k++) M[k] = T[k];
        }
    }
    if (lane == 31) {
#pragma unroll
        for (int k = 0; k < 12; k++) wTot[w][k] = M[k];
    }
    __syncthreads();

    if (w == 0) {
        float S[12];
        if (lane < 16) {
#pragma unroll
            for (int k = 0; k < 12; k++) S[k] = wTot[lane][k];
        } else {
            S[0] = 1.f; S[1] = 0.f; S[2] = 0.f;
            S[3] = 0.f; S[4] = 1.f; S[5] = 0.f;
            S[6] = 0.f; S[7] = 0.f; S[8] = 1.f;
            S[9] = 0.f; S[10] = 0.f; S[11] = 0.f;
        }
#pragma unroll
        for (int off = 1; off < 16; off <<= 1) {
            float Lf[12];
#pragma unroll
            for (int k = 0; k < 12; k++) Lf[k] = __shfl_up_sync(0xffffffffu, S[k], off);
            if (lane >= off && lane < 16) {
                float T[12];
                compose(Lf, S, T);
#pragma unroll
                for (int k = 0; k < 12; k++) S[k] = T[k];
            }
        }
        if (lane < 16) {
#pragma unroll
            for (int k = 0; k < 12; k++) wTot[lane][k] = S[k];
        }
    }
    __syncthreads();

    float Fin[12];
    if (w > 0) {
        float P[12];
#pragma unroll
        for (int k = 0; k < 12; k++) P[k] = wTot[w - 1][k];
        compose(P, M, Fin);
    } else {
#pragma unroll
        for (int k = 0; k < 12; k++) Fin[k] = M[k];
    }

    float Mp[12];
#pragma unroll
    for (int k = 0; k < 9; k++) Mp[k] = __shfl_up_sync(0xffffffffu, Fin[k], 1);
    if (lane == 0) {
        if (w == 0) {
            Mp[0] = 1.f; Mp[1] = 0.f; Mp[2] = 0.f;
            Mp[3] = 0.f; Mp[4] = 1.f; Mp[5] = 0.f;
            Mp[6] = 0.f; Mp[7] = 0.f; Mp[8] = 1.f;
        } else {
#pragma unroll
            for (int k = 0; k < 9; k++) Mp[k] = wTot[w - 1][k];
        }
    }
    Mp[9] = 0.f; Mp[10] = 0.f; Mp[11] = 0.f;

    float Mi[12];
    Mi[0] = Fin[0]; Mi[1] = Fin[3]; Mi[2] = Fin[6];
    Mi[3] = Fin[1]; Mi[4] = Fin[4]; Mi[5] = Fin[7];
    Mi[6] = Fin[2]; Mi[7] = Fin[5]; Mi[8] = Fin[8];
    Mi[9]  = -(Mi[0] * Fin[9] + Mi[1] * Fin[10] + Mi[2] * Fin[11]);
    Mi[10] = -(Mi[3] * Fin[9] + Mi[4] * Fin[10] + Mi[5] * Fin[11]);
    Mi[11] = -(Mi[6] * Fin[9] + Mi[7] * Fin[10] + Mi[8] * Fin[11]);

    float Da[12];
    Da[0] = -sa; Da[1] = -ca * cb; Da[2] = ca * sb;
    Da[3] = ca;  Da[4] = -sa * cb; Da[5] = sa * sb;
    Da[6] = 0.f; Da[7] = 0.f;      Da[8] = 0.f;
    Da[9] = -RCA * sa; Da[10] = RCA * ca; Da[11] = 0.f;

    float Db[12];
    Db[0] = 0.f; Db[1] = sa * sb;  Db[2] = sa * cb;
    Db[3] = 0.f; Db[4] = -ca * sb; Db[5] = -ca * cb;
    Db[6] = 0.f; Db[7] = cb;       Db[8] = -sb;
    Db[9] = 0.f; Db[10] = 0.f;     Db[11] = 0.f;

    float G[12], Fa[12], Fb[12];
    compose(Da, Mi, G);
    compose(Mp, G, Fa);
    compose(Db, Mi, G);
    compose(Mp, G, Fb);

    float* o = &g_F[(b * LL + l) * 24];
#pragma unroll
    for (int i = 0; i < 3; i++) {
        o[i * 4 + 0] = Fa[i * 3 + 0];
        o[i * 4 + 1] = Fa[i * 3 + 1];
        o[i * 4 + 2] = Fa[i * 3 + 2];
        o[i * 4 + 3] = Fa[9 + i];
        o[12 + i * 4 + 0] = Fb[i * 3 + 0];
        o[12 + i * 4 + 1] = Fb[i * 3 + 1];
        o[12 + i * 4 + 2] = Fb[i * 3 + 2];
        o[12 + i * 4 + 3] = Fb[9 + i];
    }
}

// Barrier-free, smem-free emit with live-range splitting.
// Thread = one aligned float4 group; zero groups take a load/FMA-free path.
__global__ __launch_bounds__(256) void emit_kernel(const int* __restrict__ lens,
                                                   float* __restrict__ out) {
    const int b   = blockIdx.y;
    const int l0  = blockIdx.x << 2;
    const int tid = threadIdx.x;
    const int len = __ldg(&lens[b]);
    const float4* C4 = g_C4 + b * LP1;
    const float4  z4 = make_float4(0.f, 0.f, 0.f, 0.f);

#pragma unroll 1
    for (int dl = 0; dl < 4; dl++) {
        const int l = l0 + dl;
        const size_t base0 = ((size_t)(b * 2 + 0) * LL + l) * ROWF;
        const size_t base1 = base0 + (size_t)LL * ROWF;
        const int head = (4 - ((3 * l) & 3)) & 3;   // 0..3

        // Live float range of this row: [3(l+1), 3(len+1)).  Group g covers
        // [head+4g, head+4g+4).  Empty for dead rows.
        int g_min = 1, g_max = 0;
        const bool alive = (l < len);
        if (alive) {
            g_min = (3 * l - head + 3) >> 2;          // ceil((3l-head)/4), >= -0
            if (g_min < 0) g_min = 0;
            g_max = (3 * len + 2 - head) >> 2;        // floor
            if (g_max > NG - 1) g_max = NG - 1;
        }

        const float4* Fp = (const float4*)&g_F[(b * LL + l) * 24];

#pragma unroll
        for (int it = 0; it < 3; it++) {
            const int t = tid + (it << 8);            // 0..767
            const int s = (t >= NG);
            const int g = t - (s ? NG : 0);
            float* gp = out + (s ? base1 : base0) + head + 4 * g;

            if (g < g_min || g > g_max) {
                __stcs((float4*)gp, z4);              // cheap zero path
                continue;
            }
            const int e0 = head + 4 * g;
            const int m0 = e0 / 3;
            const int c0 = e0 - 3 * m0;

            const float4 F0 = __ldg(&Fp[s * 3 + 0]);
            const float4 F1 = __ldg(&Fp[s * 3 + 1]);
            const float4 F2 = __ldg(&Fp[s * 3 + 2]);
            const float4 q0 = __ldg(&C4[m0]);
            const float4 q1 = __ldg(&C4[m0 + 1]);

            const bool on0 = (m0 > l) && (m0 <= len);
            const bool on1 = (m0 + 1 > l) && (m0 + 1 <= len);

            const float d00 = on0 ? (F0.x * q0.x + F0.y * q0.y + F0.z * q0.z + F0.w) : 0.f;
            const float d01 = on0 ? (F1.x * q0.x + F1.y * q0.y + F1.z * q0.z + F1.w) : 0.f;
            const float d02 = on0 ? (F2.x * q0.x + F2.y * q0.y + F2.z * q0.z + F2.w) : 0.f;
            const float d10 = on1 ? (F0.x * q1.x + F0.y * q1.y + F0.z * q1.z + F0.w) : 0.f;
            const float d11 = on1 ? (F1.x * q1.x + F1.y * q1.y + F1.z * q1.z + F1.w) : 0.f;
            const float d12 = on1 ? (F2.x * q1.x + F2.y * q1.y + F2.z * q1.z + F2.w) : 0.f;

            float4 o4;
            o4.x = (c0 == 0) ? d00 : (c0 == 1) ? d01 : d02;
            o4.y = (c0 == 0) ? d01 : (c0 == 1) ? d02 : d10;
            o4.z = (c0 == 0) ? d02 : (c0 == 1) ? d10 : d11;
            o4.w = (c0 == 0) ? d10 : (c0 == 1) ? d11 : d12;
            __stcs((float4*)gp, o4);
        }

        // 3 boundary scalars per row (head + tail = 3).
        if (tid < 6) {
            const int s  = tid >= 3;
            const int jj = tid - (s ? 3 : 0);
            const int e  = (jj < head) ? jj : (head + 4 * NG + (jj - head));
            const int m  = e / 3;
            const int c  = e - 3 * m;
            const bool on = alive && (m > l) && (m <= len);
            float val = 0.f;
            if (on) {
                const float4 Fc = __ldg(&Fp[s * 3 + c]);
                const float4 q  = __ldg(&C4[m]);
                val = Fc.x * q.x + Fc.y * q.y + Fc.z * q.z + Fc.w;
            }
            out[(s ? base1 : base0) + e] = val;
        }
    }
}

extern "C" void kernel_launch(void* const* d_in, const int* in_sizes, int n_in,
                              void* d_out, int out_size) {
    const float* angles = (const float*)d_in[0];   // (32, 2, 512)
    const float* coords = (const float*)d_in[1];   // (32, 1539)
    const int*   lens   = (const int*)d_in[2];     // (32,)
    float* out = (float*)d_out;

    scan_kernel<<<BSZ, LL>>>(angles, coords);
    emit_kernel<<<dim3(LL / 4, BSZ), 256>>>(lens, out);
}

// round 11
// speedup vs baseline: 2.3091x; 1.0773x over previous
#include <cuda_runtime.h>
#include <cuda_bf16.h>

#define LL   512
#define BSZ  32
#define LP1  513
#define ROWF 1539
#define NG   384          // aligned float4 groups per row (same for all shifts)
#define RCA  3.8f

// Scratch: Fa (12 floats, 3x4 row-major) + Fb (12 floats) per (b, l)
__device__ float g_F[BSZ * LL * 24];
// Homogeneous coords table: g_C4[b*513 + m] = (x, y, z, 1)
__device__ __align__(16) float4 g_C4[BSZ * LP1];

// Affine 3x4 stored as r[0..8] row-major + t[9..11]. C = A @ B.
__device__ __forceinline__ void compose(const float* __restrict__ A,
                                        const float* __restrict__ B,
                                        float* __restrict__ C) {
#pragma unroll
    for (int i = 0; i < 3; i++) {
        const float a0 = A[i * 3 + 0], a1 = A[i * 3 + 1], a2 = A[i * 3 + 2];
        C[i * 3 + 0] = a0 * B[0] + a1 * B[3] + a2 * B[6];
        C[i * 3 + 1] = a0 * B[1] + a1 * B[4] + a2 * B[7];
        C[i * 3 + 2] = a0 * B[2] + a1 * B[5] + a2 * B[8];
        C[9 + i]     = a0 * B[9] + a1 * B[10] + a2 * B[11] + A[9 + i];
    }
}

// One block per batch: builds coord table + warp-shuffle prefix product,
// then Fa/Fb = Rprev @ (dB @ Minv) per l.
__global__ __launch_bounds__(LL) void scan_kernel(const float* __restrict__ angles,
                                                  const float* __restrict__ coords) {
    __shared__ float wTot[16][13];
    const int b    = blockIdx.x;
    const int l    = threadIdx.x;
    const int w    = l >> 5;
    const int lane = l & 31;

    {
        const float* c = coords + (size_t)b * ROWF + 3 * l;
        g_C4[b * LP1 + l] = make_float4(c[0], c[1], c[2], 1.f);
        if (l == 0) {
            const float* c2 = coords + (size_t)b * ROWF + 3 * 512;
            g_C4[b * LP1 + 512] = make_float4(c2[0], c2[1], c2[2], 1.f);
        }
    }

    const float alpha = angles[(b * 2 + 0) * LL + l];
    const float beta  = angles[(b * 2 + 1) * LL + l];
    float sa, ca, sb, cb;
    sincosf(alpha, &sa, &ca);
    sincosf(beta,  &sb, &cb);

    float M[12];
    M[0] = ca;  M[1] = -sa * cb; M[2] = sa * sb;
    M[3] = sa;  M[4] = ca * cb;  M[5] = -ca * sb;
    M[6] = 0.f; M[7] = sb;       M[8] = cb;
    M[9] = RCA * ca; M[10] = RCA * sa; M[11] = 0.f;

#pragma unroll
    for (int off = 1; off < 32; off <<= 1) {
        float Lf[12];
#pragma unroll
        for (int k = 0; k < 12; k++) Lf[k] = __shfl_up_sync(0xffffffffu, M[k], off);
        if (lane >= off) {
            float T[12];
            compose(Lf, M, T);
#pragma unroll
            for (int k = 0; k < 12; k++) M[k] = T[k];
        }
    }
    if (lane == 31) {
#pragma unroll
        for (int k = 0; k < 12; k++) wTot[w][k] = M[k];
    }
    __syncthreads();

    if (w == 0) {
        float S[12];
        if (lane < 16) {
#pragma unroll
            for (int k = 0; k < 12; k++) S[k] = wTot[lane][k];
        } else {
            S[0] = 1.f; S[1] = 0.f; S[2] = 0.f;
            S[3] = 0.f; S[4] = 1.f; S[5] = 0.f;
            S[6] = 0.f; S[7] = 0.f; S[8] = 1.f;
            S[9] = 0.f; S[10] = 0.f; S[11] = 0.f;
        }
#pragma unroll
        for (int off = 1; off < 16; off <<= 1) {
            float Lf[12];
#pragma unroll
            for (int k = 0; k < 12; k++) Lf[k] = __shfl_up_sync(0xffffffffu, S[k], off);
            if (lane >= off && lane < 16) {
                float T[12];
                compose(Lf, S, T);
#pragma unroll
                for (int k = 0; k < 12; k++) S[k] = T[k];
            }
        }
        if (lane < 16) {
#pragma unroll
            for (int k = 0; k < 12; k++) wTot[lane][k] = S[k];
        }
    }
    __syncthreads();

    float Fin[12];
    if (w > 0) {
        float P[12];
#pragma unroll
        for (int k = 0; k < 12; k++) P[k] = wTot[w - 1][k];
        compose(P, M, Fin);
    } else {
#pragma unroll
        for (int k = 0; k < 12; k++) Fin[k] = M[k];
    }

    float Mp[12];
#pragma unroll
    for (int k = 0; k < 9; k++) Mp[k] = __shfl_up_sync(0xffffffffu, Fin[k], 1);
    if (lane == 0) {
        if (w == 0) {
            Mp[0] = 1.f; Mp[1] = 0.f; Mp[2] = 0.f;
            Mp[3] = 0.f; Mp[4] = 1.f; Mp[5] = 0.f;
            Mp[6] = 0.f; Mp[7] = 0.f; Mp[8] = 1.f;
        } else {
#pragma unroll
            for (int k = 0; k < 9; k++) Mp[k] = wTot[w - 1][k];
        }
    }
    Mp[9] = 0.f; Mp[10] = 0.f; Mp[11] = 0.f;

    float Mi[12];
    Mi[0] = Fin[0]; Mi[1] = Fin[3]; Mi[2] = Fin[6];
    Mi[3] = Fin[1]; Mi[4] = Fin[4]; Mi[5] = Fin[7];
    Mi[6] = Fin[2]; Mi[7] = Fin[5]; Mi[8] = Fin[8];
    Mi[9]  = -(Mi[0] * Fin[9] + Mi[1] * Fin[10] + Mi[2] * Fin[11]);
    Mi[10] = -(Mi[3] * Fin[9] + Mi[4] * Fin[10] + Mi[5] * Fin[11]);
    Mi[11] = -(Mi[6] * Fin[9] + Mi[7] * Fin[10] + Mi[8] * Fin[11]);

    float Da[12];
    Da[0] = -sa; Da[1] = -ca * cb; Da[2] = ca * sb;
    Da[3] = ca;  Da[4] = -sa * cb; Da[5] = sa * sb;
    Da[6] = 0.f; Da[7] = 0.f;      Da[8] = 0.f;
    Da[9] = -RCA * sa; Da[10] = RCA * ca; Da[11] = 0.f;

    float Db[12];
    Db[0] = 0.f; Db[1] = sa * sb;  Db[2] = sa * cb;
    Db[3] = 0.f; Db[4] = -ca * sb; Db[5] = -ca * cb;
    Db[6] = 0.f; Db[7] = cb;       Db[8] = -sb;
    Db[9] = 0.f; Db[10] = 0.f;     Db[11] = 0.f;

    float G[12], Fa[12], Fb[12];
    compose(Da, Mi, G);
    compose(Mp, G, Fa);
    compose(Db, Mi, G);
    compose(Mp, G, Fb);

    float* o = &g_F[(b * LL + l) * 24];
#pragma unroll
    for (int i = 0; i < 3; i++) {
        o[i * 4 + 0] = Fa[i * 3 + 0];
        o[i * 4 + 1] = Fa[i * 3 + 1];
        o[i * 4 + 2] = Fa[i * 3 + 2];
        o[i * 4 + 3] = Fa[9 + i];
        o[12 + i * 4 + 0] = Fb[i * 3 + 0];
        o[12 + i * 4 + 1] = Fb[i * 3 + 1];
        o[12 + i * 4 + 2] = Fb[i * 3 + 2];
        o[12 + i * 4 + 3] = Fb[9 + i];
    }

    __threadfence();
#if __CUDA_ARCH__ >= 900
    cudaTriggerProgrammaticLaunchCompletion();
#endif
}

// Barrier-free emit. 384 threads: thread = group g (one float4 per row-half),
// computes Fa AND Fb outputs from one coord pair. l interleaved stride-128
// across the block's 4 rows for load balance.
__global__ __launch_bounds__(384) void emit_kernel(const int* __restrict__ lens,
                                                   float* __restrict__ out) {
    const int b   = blockIdx.y;
    const int g   = threadIdx.x;           // 0..383
    const int len = __ldg(&lens[b]);
    const float4 z4 = make_float4(0.f, 0.f, 0.f, 0.f);

#if __CUDA_ARCH__ >= 900
    cudaGridDependencySynchronize();
#endif
    const float4* C4 = g_C4 + b * LP1;

#pragma unroll 1
    for (int dl = 0; dl < 4; dl++) {
        const int l = blockIdx.x + (dl << 7);          // stride-128 interleave
        const size_t base0 = ((size_t)(b * 2 + 0) * LL + l) * ROWF;
        const size_t base1 = base0 + (size_t)LL * ROWF;
        const int head = (4 - ((3 * l) & 3)) & 3;      // 0..3
        const bool alive = (l < len);

        int g_min = 1, g_max = 0;
        if (alive) {
            g_min = (3 * l - head + 3) >> 2;
            if (g_min < 0) g_min = 0;
            g_max = (3 * len + 2 - head) >> 2;
            if (g_max > NG - 1) g_max = NG - 1;
        }

        float* gp0 = out + base0 + head + 4 * g;
        float* gp1 = out + base1 + head + 4 * g;

        if (g < g_min || g > g_max) {
            __stcs((float4*)gp0, z4);
            __stcs((float4*)gp1, z4);
        } else {
            const float4* Fp = (const float4*)&g_F[(b * LL + l) * 24];
            const float4 A0 = __ldg(&Fp[0]);
            const float4 A1 = __ldg(&Fp[1]);
            const float4 A2 = __ldg(&Fp[2]);
            const float4 B0 = __ldg(&Fp[3]);
            const float4 B1 = __ldg(&Fp[4]);
            const float4 B2 = __ldg(&Fp[5]);

            const int e0 = head + 4 * g;
            const int m0 = e0 / 3;
            const int c0 = e0 - 3 * m0;
            const float4 q0 = __ldg(&C4[m0]);
            const float4 q1 = __ldg(&C4[m0 + 1]);
            const bool on0 = (m0 > l) && (m0 <= len);
            const bool on1 = (m0 + 1 > l) && (m0 + 1 <= len);

            const float a00 = on0 ? (A0.x * q0.x + A0.y * q0.y + A0.z * q0.z + A0.w) : 0.f;
            const float a01 = on0 ? (A1.x * q0.x + A1.y * q0.y + A1.z * q0.z + A1.w) : 0.f;
            const float a02 = on0 ? (A2.x * q0.x + A2.y * q0.y + A2.z * q0.z + A2.w) : 0.f;
            const float a10 = on1 ? (A0.x * q1.x + A0.y * q1.y + A0.z * q1.z + A0.w) : 0.f;
            const float a11 = on1 ? (A1.x * q1.x + A1.y * q1.y + A1.z * q1.z + A1.w) : 0.f;
            const float a12 = on1 ? (A2.x * q1.x + A2.y * q1.y + A2.z * q1.z + A2.w) : 0.f;

            const float b00 = on0 ? (B0.x * q0.x + B0.y * q0.y + B0.z * q0.z + B0.w) : 0.f;
            const float b01 = on0 ? (B1.x * q0.x + B1.y * q0.y + B1.z * q0.z + B1.w) : 0.f;
            const float b02 = on0 ? (B2.x * q0.x + B2.y * q0.y + B2.z * q0.z + B2.w) : 0.f;
            const float b10 = on1 ? (B0.x * q1.x + B0.y * q1.y + B0.z * q1.z + B0.w) : 0.f;
            const float b11 = on1 ? (B1.x * q1.x + B1.y * q1.y + B1.z * q1.z + B1.w) : 0.f;
            const float b12 = on1 ? (B2.x * q1.x + B2.y * q1.y + B2.z * q1.z + B2.w) : 0.f;

            float4 oa, ob;
            oa.x = (c0 == 0) ? a00 : (c0 == 1) ? a01 : a02;
            oa.y = (c0 == 0) ? a01 : (c0 == 1) ? a02 : a10;
            oa.z = (c0 == 0) ? a02 : (c0 == 1) ? a10 : a11;
            oa.w = (c0 == 0) ? a10 : (c0 == 1) ? a11 : a12;
            ob.x = (c0 == 0) ? b00 : (c0 == 1) ? b01 : b02;
            ob.y = (c0 == 0) ? b01 : (c0 == 1) ? b02 : b10;
            ob.z = (c0 == 0) ? b02 : (c0 == 1) ? b10 : b11;
            ob.w = (c0 == 0) ? b10 : (c0 == 1) ? b11 : b12;

            __stcs((float4*)gp0, oa);
            __stcs((float4*)gp1, ob);
        }

        // 3 boundary scalars per row-half (head + tail = 3).
        if (g < 6) {
            const int s  = g >= 3;
            const int jj = g - (s ? 3 : 0);
            const int e  = (jj < head) ? jj : (head + 4 * NG + (jj - head));
            const int m  = e / 3;
            const int c  = e - 3 * m;
            const bool on = alive && (m > l) && (m <= len);
            float val = 0.f;
            if (on) {
                const float4 Fc = __ldg(&((const float4*)&g_F[(b * LL + l) * 24])[s * 3 + c]);
                const float4 q  = __ldg(&C4[m]);
                val = Fc.x * q.x + Fc.y * q.y + Fc.z * q.z + Fc.w;
            }
            out[(s ? base1 : base0) + e] = val;
        }
    }
}

extern "C" void kernel_launch(void* const* d_in, const int* in_sizes, int n_in,
                              void* d_out, int out_size) {
    const float* angles = (const float*)d_in[0];   // (32, 2, 512)
    const float* coords = (const float*)d_in[1];   // (32, 1539)
    const int*   lens   = (const int*)d_in[2];     // (32,)
    float* out = (float*)d_out;

    scan_kernel<<<BSZ, LL>>>(angles, coords);

    // Emit with programmatic dependent launch: overlaps its prelude with the
    // scan tail; cudaGridDependencySynchronize() guards g_F/g_C4 reads.
    cudaLaunchConfig_t cfg = {};
    cfg.gridDim  = dim3(128, BSZ);
    cfg.blockDim = dim3(384);
    cfg.dynamicSmemBytes = 0;
    cfg.stream = 0;
    cudaLaunchAttribute attr[1];
    attr[0].id = cudaLaunchAttributeProgrammaticStreamSerialization;
    attr[0].val.programmaticStreamSerializationAllowed = 1;
    cfg.attrs = attr;
    cfg.numAttrs = 1;
    cudaLaunchKernelEx(&cfg, emit_kernel, lens, out);
}